// round 1
// baseline (speedup 1.0000x reference)
#include <cuda_runtime.h>
#include <math.h>

#define HH 768
#define NHD 8
#define HDD 96
#define BB 64
#define SS 512
#define LL 511
#define NROWS (BB*LL)          // 32704
#define BUF_ELEMS (NROWS*HH)   // 25116672
#define COMMA_ID 1010

// ---------------- scratch (device globals; no allocation allowed) ----------
static __device__ float g_q[BUF_ELEMS];      // [b][h][l][d]
static __device__ float g_k[BUF_ELEMS];
static __device__ float g_v[BUF_ELEMS];
static __device__ float g_ctx[BUF_ELEMS];    // [row=b*511+l][H]
static __device__ float g_ao[BUF_ELEMS];     // attn_out, same layout as ctx
static __device__ float g_fv[NROWS];
static __device__ double g_chsum[HH];
static __device__ double g_chsumsq[HH];
static __device__ float g_g[HH];
static __device__ float g_c0;

// ---------------- zero stats ----------------
__global__ void zero_stats_kernel() {
    int i = threadIdx.x;
    if (i < HH) { g_chsum[i] = 0.0; g_chsumsq[i] = 0.0; }
}

// ---------------- fused QKV GEMM -------------------------------------------
// C[M=32704, N=768] = A @ W^T + bias, for 3 (A,W) pairs selected by blockIdx.y.
// BM=128, BN=128, BK=16, 256 threads, 8x8 microtile.
#define BM 128
#define BN 128
#define BKK 16

__global__ __launch_bounds__(256) void qkv_gemm_kernel(
    const float* __restrict__ text, const float* __restrict__ cols,
    const float* __restrict__ wq, const float* __restrict__ wk, const float* __restrict__ wv,
    const float* __restrict__ bq, const float* __restrict__ bk, const float* __restrict__ bv)
{
    __shared__ float As[BKK][BM];
    __shared__ float Bs[BKK][BN];

    int mt = blockIdx.x;
    int nt = blockIdx.y;            // 0..17
    int sec = nt / 6;               // 0=q, 1=k, 2=v
    int nb  = (nt % 6) * BN;

    const float* A    = (sec == 0) ? cols : text;
    const float* W    = (sec == 0) ? wq : (sec == 1 ? wk : wv);
    const float* bias = (sec == 0) ? bq : (sec == 1 ? bk : bv);
    float* out        = (sec == 0) ? g_q : (sec == 1 ? g_k : g_v);

    int tid = threadIdx.x;
    int tx = tid & 15;
    int ty = tid >> 4;
    int m0 = mt * BM;

    float acc[8][8];
#pragma unroll
    for (int i = 0; i < 8; i++)
#pragma unroll
        for (int j = 0; j < 8; j++) acc[i][j] = 0.f;

    for (int k0 = 0; k0 < HH; k0 += BKK) {
        // load A tile (transposed into As[k][m]); 512 float4 / 256 threads
#pragma unroll
        for (int u = 0; u < 2; u++) {
            int idx = tid + u * 256;
            int r = idx >> 2;
            int kc = (idx & 3) * 4;
            int row = m0 + r;
            if (row >= NROWS) row = 0;  // results for these rows are discarded
            int b = row / LL, l = row % LL;
            const float4 va = *(const float4*)(A + ((size_t)(b * SS + l + 1)) * HH + k0 + kc);
            As[kc + 0][r] = va.x; As[kc + 1][r] = va.y;
            As[kc + 2][r] = va.z; As[kc + 3][r] = va.w;
        }
        // load W tile (Bs[k][n] = W[nb+n][k0+k])
#pragma unroll
        for (int u = 0; u < 2; u++) {
            int idx = tid + u * 256;
            int n = idx >> 2;
            int kc = (idx & 3) * 4;
            const float4 vw = *(const float4*)(W + (size_t)(nb + n) * HH + k0 + kc);
            Bs[kc + 0][n] = vw.x; Bs[kc + 1][n] = vw.y;
            Bs[kc + 2][n] = vw.z; Bs[kc + 3][n] = vw.w;
        }
        __syncthreads();
#pragma unroll
        for (int kk = 0; kk < BKK; kk++) {
            float a[8], b2[8];
#pragma unroll
            for (int i = 0; i < 8; i++) a[i]  = As[kk][ty + 16 * i];
#pragma unroll
            for (int j = 0; j < 8; j++) b2[j] = Bs[kk][tx + 16 * j];
#pragma unroll
            for (int i = 0; i < 8; i++)
#pragma unroll
                for (int j = 0; j < 8; j++) acc[i][j] += a[i] * b2[j];
        }
        __syncthreads();
    }

    // epilogue: write into [b][h][l][d] layout
#pragma unroll
    for (int i = 0; i < 8; i++) {
        int row = m0 + ty + 16 * i;
        if (row >= NROWS) continue;
        int b = row / LL, l = row % LL;
#pragma unroll
        for (int j = 0; j < 8; j++) {
            int n = nb + tx + 16 * j;
            float v = acc[i][j] + bias[n];
            int h = n / HDD, d = n % HDD;
            out[(((size_t)(b * NHD + h)) * LL + l) * HDD + d] = v;
        }
    }
}

// ---------------- flash attention ------------------------------------------
// grid (16 q-tiles, 512 bh), block 128. BQ=BKT=32. Output ctx in [row][H].
#define BQ 32
#define BKT 32

__global__ __launch_bounds__(128) void attn_kernel()
{
    int qt = blockIdx.x;
    int bh = blockIdx.y;
    int b = bh >> 3, h = bh & 7;
    const float* Q = g_q + (size_t)bh * LL * HDD;
    const float* K = g_k + (size_t)bh * LL * HDD;
    const float* V = g_v + (size_t)bh * LL * HDD;

    __shared__ float Qs[BQ][97];
    __shared__ float Ks[BKT][97];
    __shared__ float Vs[BKT][97];
    __shared__ float Ps[BQ][33];

    int tid = threadIdx.x;
    int tx = tid & 7;
    int ty = tid >> 3;

    for (int idx = tid; idx < BQ * HDD; idx += 128) {
        int r = idx / HDD, d = idx % HDD;
        int qg = qt * BQ + r; if (qg > LL - 1) qg = LL - 1;
        Qs[r][d] = Q[(size_t)qg * HDD + d];
    }

    float m_i[2] = { -1e30f, -1e30f };
    float l_i[2] = { 0.f, 0.f };
    float O[2][12];
#pragma unroll
    for (int i = 0; i < 2; i++)
#pragma unroll
        for (int jj = 0; jj < 12; jj++) O[i][jj] = 0.f;

    const float scale = 0.10206207261596575f;  // 1/sqrt(96)

    for (int kt = 0; kt < 16; kt++) {
        __syncthreads();
        for (int idx = tid; idx < BKT * HDD; idx += 128) {
            int r = idx / HDD, d = idx % HDD;
            int kg = kt * BKT + r;
            float kv = 0.f, vv = 0.f;
            if (kg < LL) { kv = K[(size_t)kg * HDD + d]; vv = V[(size_t)kg * HDD + d]; }
            Ks[r][d] = kv; Vs[r][d] = vv;
        }
        __syncthreads();

        float Sv[2][4];
#pragma unroll
        for (int i = 0; i < 2; i++)
#pragma unroll
            for (int j = 0; j < 4; j++) Sv[i][j] = 0.f;

        for (int d = 0; d < HDD; d++) {
            float qv0 = Qs[ty * 2 + 0][d];
            float qv1 = Qs[ty * 2 + 1][d];
            float kv[4];
#pragma unroll
            for (int j = 0; j < 4; j++) kv[j] = Ks[tx * 4 + j][d];
#pragma unroll
            for (int j = 0; j < 4; j++) { Sv[0][j] += qv0 * kv[j]; Sv[1][j] += qv1 * kv[j]; }
        }
#pragma unroll
        for (int i = 0; i < 2; i++)
#pragma unroll
            for (int j = 0; j < 4; j++) {
                int cg = kt * BKT + tx * 4 + j;
                Sv[i][j] = (cg < LL) ? Sv[i][j] * scale : -1e30f;
            }

#pragma unroll
        for (int i = 0; i < 2; i++) {
            float mt = fmaxf(fmaxf(Sv[i][0], Sv[i][1]), fmaxf(Sv[i][2], Sv[i][3]));
            mt = fmaxf(mt, __shfl_xor_sync(0xffffffffu, mt, 1));
            mt = fmaxf(mt, __shfl_xor_sync(0xffffffffu, mt, 2));
            mt = fmaxf(mt, __shfl_xor_sync(0xffffffffu, mt, 4));
            float mn = fmaxf(m_i[i], mt);
            float alpha = expf(m_i[i] - mn);
            float rs = 0.f;
#pragma unroll
            for (int j = 0; j < 4; j++) {
                float p = expf(Sv[i][j] - mn);
                Ps[ty * 2 + i][tx * 4 + j] = p;
                rs += p;
            }
            rs += __shfl_xor_sync(0xffffffffu, rs, 1);
            rs += __shfl_xor_sync(0xffffffffu, rs, 2);
            rs += __shfl_xor_sync(0xffffffffu, rs, 4);
            l_i[i] = l_i[i] * alpha + rs;
            m_i[i] = mn;
#pragma unroll
            for (int jj = 0; jj < 12; jj++) O[i][jj] *= alpha;
        }
        __syncthreads();

        // P @ V
        for (int k = 0; k < BKT; k++) {
            float p0 = Ps[ty * 2 + 0][k];
            float p1 = Ps[ty * 2 + 1][k];
#pragma unroll
            for (int jj = 0; jj < 12; jj++) {
                float vv = Vs[k][tx + 8 * jj];
                O[0][jj] += p0 * vv;
                O[1][jj] += p1 * vv;
            }
        }
    }

#pragma unroll
    for (int i = 0; i < 2; i++) {
        int qg = qt * BQ + ty * 2 + i;
        if (qg >= LL) continue;
        float inv = 1.0f / l_i[i];
        size_t base = ((size_t)(b * LL + qg)) * HH + h * HDD;
#pragma unroll
        for (int jj = 0; jj < 12; jj++)
            g_ctx[base + tx + 8 * jj] = O[i][jj] * inv;
    }
}

// ---------------- wo GEMM + per-channel sum/sumsq epilogue ------------------
__global__ __launch_bounds__(256) void wo_gemm_kernel(
    const float* __restrict__ wo, const float* __restrict__ bo)
{
    __shared__ float As[BKK][BM];
    __shared__ float Bs[BKK][BN];
    __shared__ float scol[BN];
    __shared__ float scolq[BN];

    int mt = blockIdx.x;
    int nb = blockIdx.y * BN;

    int tid = threadIdx.x;
    int tx = tid & 15;
    int ty = tid >> 4;
    int m0 = mt * BM;

    if (tid < BN) { scol[tid] = 0.f; scolq[tid] = 0.f; }

    float acc[8][8];
#pragma unroll
    for (int i = 0; i < 8; i++)
#pragma unroll
        for (int j = 0; j < 8; j++) acc[i][j] = 0.f;

    for (int k0 = 0; k0 < HH; k0 += BKK) {
#pragma unroll
        for (int u = 0; u < 2; u++) {
            int idx = tid + u * 256;
            int r = idx >> 2;
            int kc = (idx & 3) * 4;
            int row = m0 + r;
            if (row >= NROWS) row = 0;
            const float4 va = *(const float4*)(g_ctx + (size_t)row * HH + k0 + kc);
            As[kc + 0][r] = va.x; As[kc + 1][r] = va.y;
            As[kc + 2][r] = va.z; As[kc + 3][r] = va.w;
        }
#pragma unroll
        for (int u = 0; u < 2; u++) {
            int idx = tid + u * 256;
            int n = idx >> 2;
            int kc = (idx & 3) * 4;
            const float4 vw = *(const float4*)(wo + (size_t)(nb + n) * HH + k0 + kc);
            Bs[kc + 0][n] = vw.x; Bs[kc + 1][n] = vw.y;
            Bs[kc + 2][n] = vw.z; Bs[kc + 3][n] = vw.w;
        }
        __syncthreads();
#pragma unroll
        for (int kk = 0; kk < BKK; kk++) {
            float a[8], b2[8];
#pragma unroll
            for (int i = 0; i < 8; i++) a[i]  = As[kk][ty + 16 * i];
#pragma unroll
            for (int j = 0; j < 8; j++) b2[j] = Bs[kk][tx + 16 * j];
#pragma unroll
            for (int i = 0; i < 8; i++)
#pragma unroll
                for (int j = 0; j < 8; j++) acc[i][j] += a[i] * b2[j];
        }
        __syncthreads();
    }

#pragma unroll
    for (int j = 0; j < 8; j++) {
        int nl = tx + 16 * j;
        int n = nb + nl;
        float bias = bo[n];
        float s = 0.f, sq = 0.f;
#pragma unroll
        for (int i = 0; i < 8; i++) {
            int row = m0 + ty + 16 * i;
            if (row >= NROWS) continue;
            float v = acc[i][j] + bias;
            g_ao[(size_t)row * HH + n] = v;
            s += v;
            sq += v * v;
        }
        atomicAdd(&scol[nl], s);
        atomicAdd(&scolq[nl], sq);
    }
    __syncthreads();
    if (tid < BN) {
        atomicAdd(&g_chsum[nb + tid], (double)scol[tid]);
        atomicAdd(&g_chsumsq[nb + tid], (double)scolq[tid]);
    }
}

// ---------------- finalize: mu/var -> g, C0 --------------------------------
__global__ void finalize_kernel(const float* __restrict__ gamma,
                                const float* __restrict__ beta,
                                const float* __restrict__ w_out,
                                const float* __restrict__ b_out)
{
    __shared__ float red[HH];
    int h = threadIdx.x;
    const double N = (double)NROWS;
    double mu  = g_chsum[h] / N;
    double var = g_chsumsq[h] / N - mu * mu;
    double inv = 1.0 / sqrt(var + 1e-5);
    float g = w_out[h] * gamma[h] * (float)inv;
    g_g[h] = g;
    red[h] = w_out[h] * beta[h] - g * (float)mu;
    __syncthreads();
    if (h < 256) red[h] += red[h + 512];
    __syncthreads();
    for (int s = 256; s > 0; s >>= 1) {
        if (h < s) red[h] += red[h + s];
        __syncthreads();
    }
    if (h == 0) g_c0 = red[0] + b_out[0];
}

// ---------------- fv = c . w_out + attn_out . g + C0 -----------------------
__global__ __launch_bounds__(256) void fv_kernel(const float* __restrict__ cols,
                                                 const float* __restrict__ w_out)
{
    int warp = (blockIdx.x * 256 + threadIdx.x) >> 5;
    int lane = threadIdx.x & 31;
    if (warp >= NROWS) return;
    int b = warp / LL, l = warp % LL;
    const float* crow = cols + ((size_t)(b * SS) + l + 1) * HH;
    const float* arow = g_ao + (size_t)warp * HH;
    float s = 0.f;
    for (int k = lane; k < HH; k += 32)
        s += crow[k] * w_out[k] + arow[k] * g_g[k];
#pragma unroll
    for (int o = 16; o > 0; o >>= 1) s += __shfl_xor_sync(0xffffffffu, s, o);
    if (lane == 0) g_fv[warp] = s + g_c0;
}

// ---------------- segment pooling -------------------------------------------
__global__ void segpool_kernel(const int* __restrict__ ids, float* __restrict__ out, int nseg)
{
    int b = blockIdx.x;
    __shared__ int sc[512];
    __shared__ float ssum[32];
    __shared__ float scnt[32];
    int l = threadIdx.x;  // 0..511
    int ic = 0;
    if (l < LL) ic = (ids[b * SS + l] == COMMA_ID) ? 1 : 0;
    sc[l] = ic;
    __syncthreads();
    // inclusive Hillis-Steele scan
    for (int off = 1; off < 512; off <<= 1) {
        int v = (l >= off) ? sc[l - off] : 0;
        __syncthreads();
        sc[l] += v;
        __syncthreads();
    }
    int seg = sc[l] - ic;
    if (l < 32) { ssum[l] = 0.f; scnt[l] = 0.f; }
    __syncthreads();
    if (l >= 1 && l < LL && !ic && seg < nseg) {
        atomicAdd(&ssum[seg], g_fv[(size_t)b * LL + l]);
        atomicAdd(&scnt[seg], 1.0f);
    }
    __syncthreads();
    if (l < nseg) out[b * nseg + l] = ssum[l] / fmaxf(scnt[l], 1.0f);
}

// ---------------- launch -----------------------------------------------------
extern "C" void kernel_launch(void* const* d_in, const int* in_sizes, int n_in,
                              void* d_out, int out_size)
{
    const float* text   = (const float*)d_in[0];
    const float* cols   = (const float*)d_in[1];
    const float* wq     = (const float*)d_in[2];
    const float* wk     = (const float*)d_in[3];
    const float* wv     = (const float*)d_in[4];
    const float* bq     = (const float*)d_in[5];
    const float* bk     = (const float*)d_in[6];
    const float* bv     = (const float*)d_in[7];
    const float* wo     = (const float*)d_in[8];
    const float* bo     = (const float*)d_in[9];
    const float* gamma  = (const float*)d_in[10];
    const float* beta   = (const float*)d_in[11];
    const float* w_out  = (const float*)d_in[12];
    const float* b_out  = (const float*)d_in[13];
    const int*   ids    = (const int*)d_in[14];
    float* out = (float*)d_out;
    int nseg = out_size / BB;   // 17

    zero_stats_kernel<<<1, HH>>>();
    qkv_gemm_kernel<<<dim3(256, 18), 256>>>(text, cols, wq, wk, wv, bq, bk, bv);
    attn_kernel<<<dim3(16, 512), 128>>>();
    wo_gemm_kernel<<<dim3(256, 6), 256>>>(wo, bo);
    finalize_kernel<<<1, HH>>>(gamma, beta, w_out, b_out);
    fv_kernel<<<(NROWS + 7) / 8, 256>>>(cols, w_out);
    segpool_kernel<<<BB, 512>>>(ids, out, nseg);
}

// round 2
// speedup vs baseline: 2.5785x; 2.5785x over previous
#include <cuda_runtime.h>
#include <math.h>

#define HH 768
#define NHD 8
#define HDD 96
#define BB 64
#define SS 512
#define LL 511
#define NROWS (BB*LL)          // 32704
#define BUF_ELEMS (NROWS*HH)   // 25116672
#define COMMA_ID 1010

// ---------------- scratch (device globals; no allocation allowed) ----------
static __device__ float g_q[BUF_ELEMS];      // [b][h][l][d]
static __device__ float g_k[BUF_ELEMS];
static __device__ float g_v[BUF_ELEMS];
static __device__ float g_ctx[BUF_ELEMS];    // [row=b*511+l][H]
static __device__ float g_ao[BUF_ELEMS];     // attn_out, same layout as ctx
static __device__ float g_fv[NROWS];
static __device__ double g_chsum[HH];
static __device__ double g_chsumsq[HH];
static __device__ float g_g[HH];
static __device__ float g_c0;

// ---------------- tf32 helpers ----------------
__device__ __forceinline__ float f2tf32(float x) {
    unsigned r;
    asm("cvt.rna.tf32.f32 %0, %1;" : "=r"(r) : "f"(x));
    return __uint_as_float(r);
}
__device__ __forceinline__ unsigned uldf(const float* p) {
    return __float_as_uint(*p);
}
__device__ __forceinline__ void mma_tf32(float c[4],
    unsigned a0, unsigned a1, unsigned a2, unsigned a3,
    unsigned b0, unsigned b1)
{
    asm volatile(
        "mma.sync.aligned.m16n8k8.row.col.f32.tf32.tf32.f32 "
        "{%0,%1,%2,%3}, {%4,%5,%6,%7}, {%8,%9}, {%0,%1,%2,%3};"
        : "+f"(c[0]), "+f"(c[1]), "+f"(c[2]), "+f"(c[3])
        : "r"(a0), "r"(a1), "r"(a2), "r"(a3), "r"(b0), "r"(b1));
}

// ---------------- zero stats ----------------
__global__ void zero_stats_kernel() {
    int i = threadIdx.x;
    if (i < HH) { g_chsum[i] = 0.0; g_chsumsq[i] = 0.0; }
}

// ============================================================================
// TF32 tensor-core GEMM: C[M=32704, N=768] = A @ W^T + bias
// BM=128, BN=128, BK=32, 256 threads (8 warps, 2x4), warp tile 64x32,
// per-warp 4x4 grid of m16n8k8 mma.
// Shared tiles stored [k][m] / [k][n] with row stride 136 (136%32==8 ->
// fragment load banks tig*8+g are all distinct).
// ============================================================================
#define GBM 128
#define GBN 128
#define GBK 32
#define GLD 136

// A loader: returns value of A[row][k] for the logical matrix (handles the
// b*SS+l+1 indexing for the activation inputs).
__device__ __forceinline__ void gemm_load_tiles(
    const float* __restrict__ A, bool a_is_seq,   // seq layout: (b*SS+l+1)*HH
    const float* __restrict__ W,
    float As[GBK][GLD], float Bs[GBK][GLD],
    int m0, int nb, int k0, int tid)
{
    int r  = tid >> 1;             // 0..127
    int c0 = (tid & 1) * 16;       // float offset 0 or 16

    // A tile
    int row = m0 + r;
    if (row >= NROWS) row = 0;
    const float* arow;
    if (a_is_seq) {
        int b = row / LL, l = row % LL;
        arow = A + ((size_t)(b * SS + l + 1)) * HH;
    } else {
        arow = A + (size_t)row * HH;
    }
#pragma unroll
    for (int u = 0; u < 4; u++) {
        int kc = c0 + u * 4;
        float4 v = *(const float4*)(arow + k0 + kc);
        As[kc + 0][r] = f2tf32(v.x);
        As[kc + 1][r] = f2tf32(v.y);
        As[kc + 2][r] = f2tf32(v.z);
        As[kc + 3][r] = f2tf32(v.w);
    }
    // W tile (Bs[k][n] = W[nb+n][k0+k])
    const float* wrow = W + (size_t)(nb + r) * HH;
#pragma unroll
    for (int u = 0; u < 4; u++) {
        int kc = c0 + u * 4;
        float4 v = *(const float4*)(wrow + k0 + kc);
        Bs[kc + 0][r] = f2tf32(v.x);
        Bs[kc + 1][r] = f2tf32(v.y);
        Bs[kc + 2][r] = f2tf32(v.z);
        Bs[kc + 3][r] = f2tf32(v.w);
    }
}

__device__ __forceinline__ void gemm_mainloop(
    float acc[4][4][4], const float As[GBK][GLD], const float Bs[GBK][GLD],
    int mbase, int nbase, int g, int tig)
{
#pragma unroll
    for (int ks = 0; ks < 4; ks++) {
        unsigned a[4][4];
#pragma unroll
        for (int mt = 0; mt < 4; mt++) {
            int mm = mbase + mt * 16 + g;
            a[mt][0] = uldf(&As[ks * 8 + tig    ][mm    ]);
            a[mt][1] = uldf(&As[ks * 8 + tig    ][mm + 8]);
            a[mt][2] = uldf(&As[ks * 8 + tig + 4][mm    ]);
            a[mt][3] = uldf(&As[ks * 8 + tig + 4][mm + 8]);
        }
        unsigned bfr[4][2];
#pragma unroll
        for (int nt = 0; nt < 4; nt++) {
            int nn = nbase + nt * 8 + g;
            bfr[nt][0] = uldf(&Bs[ks * 8 + tig    ][nn]);
            bfr[nt][1] = uldf(&Bs[ks * 8 + tig + 4][nn]);
        }
#pragma unroll
        for (int mt = 0; mt < 4; mt++)
#pragma unroll
            for (int nt = 0; nt < 4; nt++)
                mma_tf32(acc[mt][nt], a[mt][0], a[mt][1], a[mt][2], a[mt][3],
                         bfr[nt][0], bfr[nt][1]);
    }
}

// ---- QKV GEMM: grid (256, 18) ----
__global__ __launch_bounds__(256) void qkv_gemm_kernel(
    const float* __restrict__ text, const float* __restrict__ cols,
    const float* __restrict__ wq, const float* __restrict__ wk, const float* __restrict__ wv,
    const float* __restrict__ bq, const float* __restrict__ bk, const float* __restrict__ bv)
{
    __shared__ float As[GBK][GLD];
    __shared__ float Bs[GBK][GLD];

    int nt_blk = blockIdx.y;
    int sec = nt_blk / 6;
    int nb  = (nt_blk % 6) * GBN;
    const float* A    = (sec == 0) ? cols : text;
    const float* W    = (sec == 0) ? wq : (sec == 1 ? wk : wv);
    const float* bias = (sec == 0) ? bq : (sec == 1 ? bk : bv);
    float* out        = (sec == 0) ? g_q : (sec == 1 ? g_k : g_v);

    int tid  = threadIdx.x;
    int lane = tid & 31, warp = tid >> 5;
    int g = lane >> 2, tig = lane & 3;
    int mbase = (warp >> 2) * 64, nbase = (warp & 3) * 32;
    int m0 = blockIdx.x * GBM;

    float acc[4][4][4];
#pragma unroll
    for (int a = 0; a < 4; a++)
#pragma unroll
        for (int b = 0; b < 4; b++)
#pragma unroll
            for (int c = 0; c < 4; c++) acc[a][b][c] = 0.f;

    for (int k0 = 0; k0 < HH; k0 += GBK) {
        gemm_load_tiles(A, true, W, As, Bs, m0, nb, k0, tid);
        __syncthreads();
        gemm_mainloop(acc, As, Bs, mbase, nbase, g, tig);
        __syncthreads();
    }

    // epilogue -> [b][h][l][d]
#pragma unroll
    for (int mt = 0; mt < 4; mt++) {
        int row0 = m0 + mbase + mt * 16 + g;
        int row1 = row0 + 8;
#pragma unroll
        for (int nt = 0; nt < 4; nt++) {
            int col0 = nb + nbase + nt * 8 + 2 * tig;
            float bi0 = bias[col0], bi1 = bias[col0 + 1];
            int h0 = col0 / HDD, d0 = col0 % HDD;
            int h1 = (col0 + 1) / HDD, d1 = (col0 + 1) % HDD;
            if (row0 < NROWS) {
                int b = row0 / LL, l = row0 % LL;
                out[(((size_t)(b * NHD + h0)) * LL + l) * HDD + d0] = acc[mt][nt][0] + bi0;
                out[(((size_t)(b * NHD + h1)) * LL + l) * HDD + d1] = acc[mt][nt][1] + bi1;
            }
            if (row1 < NROWS) {
                int b = row1 / LL, l = row1 % LL;
                out[(((size_t)(b * NHD + h0)) * LL + l) * HDD + d0] = acc[mt][nt][2] + bi0;
                out[(((size_t)(b * NHD + h1)) * LL + l) * HDD + d1] = acc[mt][nt][3] + bi1;
            }
        }
    }
}

// ---- wo GEMM + per-channel stats: grid (256, 6) ----
__global__ __launch_bounds__(256) void wo_gemm_kernel(
    const float* __restrict__ wo, const float* __restrict__ bo)
{
    __shared__ float As[GBK][GLD];
    __shared__ float Bs[GBK][GLD];
    __shared__ float scol[GBN];
    __shared__ float scolq[GBN];

    int nb = blockIdx.y * GBN;
    int tid  = threadIdx.x;
    int lane = tid & 31, warp = tid >> 5;
    int g = lane >> 2, tig = lane & 3;
    int mbase = (warp >> 2) * 64, nbase = (warp & 3) * 32;
    int m0 = blockIdx.x * GBM;

    if (tid < GBN) { scol[tid] = 0.f; scolq[tid] = 0.f; }

    float acc[4][4][4];
#pragma unroll
    for (int a = 0; a < 4; a++)
#pragma unroll
        for (int b = 0; b < 4; b++)
#pragma unroll
            for (int c = 0; c < 4; c++) acc[a][b][c] = 0.f;

    for (int k0 = 0; k0 < HH; k0 += GBK) {
        gemm_load_tiles(g_ctx, false, wo, As, Bs, m0, nb, k0, tid);
        __syncthreads();
        gemm_mainloop(acc, As, Bs, mbase, nbase, g, tig);
        __syncthreads();
    }

#pragma unroll
    for (int nt = 0; nt < 4; nt++) {
        int nl0 = nbase + nt * 8 + 2 * tig;   // local column in [0,128)
        int n0 = nb + nl0;
        float bi0 = bo[n0], bi1 = bo[n0 + 1];
        float s0 = 0.f, q0 = 0.f, s1 = 0.f, q1 = 0.f;
#pragma unroll
        for (int mt = 0; mt < 4; mt++) {
            int row0 = m0 + mbase + mt * 16 + g;
            int row1 = row0 + 8;
            if (row0 < NROWS) {
                float v0 = acc[mt][nt][0] + bi0;
                float v1 = acc[mt][nt][1] + bi1;
                g_ao[(size_t)row0 * HH + n0]     = v0;
                g_ao[(size_t)row0 * HH + n0 + 1] = v1;
                s0 += v0; q0 += v0 * v0; s1 += v1; q1 += v1 * v1;
            }
            if (row1 < NROWS) {
                float v0 = acc[mt][nt][2] + bi0;
                float v1 = acc[mt][nt][3] + bi1;
                g_ao[(size_t)row1 * HH + n0]     = v0;
                g_ao[(size_t)row1 * HH + n0 + 1] = v1;
                s0 += v0; q0 += v0 * v0; s1 += v1; q1 += v1 * v1;
            }
        }
        atomicAdd(&scol[nl0], s0);  atomicAdd(&scolq[nl0], q0);
        atomicAdd(&scol[nl0 + 1], s1); atomicAdd(&scolq[nl0 + 1], q1);
    }
    __syncthreads();
    if (tid < GBN) {
        atomicAdd(&g_chsum[nb + tid], (double)scol[tid]);
        atomicAdd(&g_chsumsq[nb + tid], (double)scolq[tid]);
    }
}

// ============================================================================
// TF32 MMA flash attention. Block = 128 threads (4 warps), one (b,h) per
// blockIdx.y, q-tile of 64 per blockIdx.x. BKT=64. Q fragments in registers.
// ============================================================================
#define KS_LD 100   // Ks row stride  (100%32==4 -> b-frag banks 4g+tig unique)
#define VS_LD 104   // Vs row stride  (104%32==8 -> b-frag banks 8tig+g unique)
#define PS_LD 68    // Ps row stride  (68%32==4  -> a-frag banks 4g+tig unique)
#define ATTN_SMEM ((64*KS_LD + 64*VS_LD + 64*PS_LD) * 4)

__global__ __launch_bounds__(128) void attn_kernel()
{
    extern __shared__ float sm[];
    float (*Ks)[KS_LD] = (float (*)[KS_LD])sm;
    float (*Vs)[VS_LD] = (float (*)[VS_LD])(sm + 64 * KS_LD);
    float (*Ps)[PS_LD] = (float (*)[PS_LD])(sm + 64 * KS_LD + 64 * VS_LD);

    int qt = blockIdx.x;
    int bh = blockIdx.y;
    int b = bh >> 3, h = bh & 7;
    const float* Q = g_q + (size_t)bh * LL * HDD;
    const float* K = g_k + (size_t)bh * LL * HDD;
    const float* V = g_v + (size_t)bh * LL * HDD;

    int tid  = threadIdx.x;
    int lane = tid & 31, warp = tid >> 5;
    int g = lane >> 2, tig = lane & 3;
    int mrow = warp * 16;

    // ---- stage Q tile (64 x 96) through Ks, then read A-fragments ----
    for (int idx = tid; idx < 64 * 24; idx += 128) {
        int r = idx / 24, c = (idx % 24) * 4;
        int qg = qt * 64 + r; if (qg > LL - 1) qg = LL - 1;
        float4 v = *(const float4*)(Q + (size_t)qg * HDD + c);
        Ks[r][c + 0] = f2tf32(v.x); Ks[r][c + 1] = f2tf32(v.y);
        Ks[r][c + 2] = f2tf32(v.z); Ks[r][c + 3] = f2tf32(v.w);
    }
    __syncthreads();

    unsigned qa[12][4];
#pragma unroll
    for (int ks = 0; ks < 12; ks++) {
        qa[ks][0] = uldf(&Ks[mrow + g    ][ks * 8 + tig    ]);
        qa[ks][1] = uldf(&Ks[mrow + g + 8][ks * 8 + tig    ]);
        qa[ks][2] = uldf(&Ks[mrow + g    ][ks * 8 + tig + 4]);
        qa[ks][3] = uldf(&Ks[mrow + g + 8][ks * 8 + tig + 4]);
    }

    float O[12][4];
#pragma unroll
    for (int nt = 0; nt < 12; nt++)
#pragma unroll
        for (int c = 0; c < 4; c++) O[nt][c] = 0.f;
    float m0v = -1e30f, m1v = -1e30f, l0 = 0.f, l1 = 0.f;

    const float scale = 0.10206207261596575f;  // 1/sqrt(96)

    for (int kt = 0; kt < 8; kt++) {
        int ktb = kt * 64;
        __syncthreads();
        // load K and V tiles (zero-pad rows >= LL)
        for (int idx = tid; idx < 64 * 24; idx += 128) {
            int r = idx / 24, c = (idx % 24) * 4;
            int kg = ktb + r;
            if (kg < LL) {
                float4 kv = *(const float4*)(K + (size_t)kg * HDD + c);
                float4 vv = *(const float4*)(V + (size_t)kg * HDD + c);
                Ks[r][c+0]=f2tf32(kv.x); Ks[r][c+1]=f2tf32(kv.y);
                Ks[r][c+2]=f2tf32(kv.z); Ks[r][c+3]=f2tf32(kv.w);
                Vs[r][c+0]=f2tf32(vv.x); Vs[r][c+1]=f2tf32(vv.y);
                Vs[r][c+2]=f2tf32(vv.z); Vs[r][c+3]=f2tf32(vv.w);
            } else {
                Ks[r][c+0]=0.f; Ks[r][c+1]=0.f; Ks[r][c+2]=0.f; Ks[r][c+3]=0.f;
                Vs[r][c+0]=0.f; Vs[r][c+1]=0.f; Vs[r][c+2]=0.f; Vs[r][c+3]=0.f;
            }
        }
        __syncthreads();

        // ---- S = Q @ K^T (warp: 16 x 64) ----
        float s[8][4];
#pragma unroll
        for (int nt = 0; nt < 8; nt++)
#pragma unroll
            for (int c = 0; c < 4; c++) s[nt][c] = 0.f;

#pragma unroll
        for (int ks = 0; ks < 12; ks++) {
#pragma unroll
            for (int nt = 0; nt < 8; nt++) {
                unsigned b0 = uldf(&Ks[nt * 8 + g][ks * 8 + tig    ]);
                unsigned b1 = uldf(&Ks[nt * 8 + g][ks * 8 + tig + 4]);
                mma_tf32(s[nt], qa[ks][0], qa[ks][1], qa[ks][2], qa[ks][3], b0, b1);
            }
        }

        // scale + mask
#pragma unroll
        for (int nt = 0; nt < 8; nt++) {
            int col = ktb + nt * 8 + 2 * tig;
            s[nt][0] = (col     < LL) ? s[nt][0] * scale : -1e30f;
            s[nt][1] = (col + 1 < LL) ? s[nt][1] * scale : -1e30f;
            s[nt][2] = (col     < LL) ? s[nt][2] * scale : -1e30f;
            s[nt][3] = (col + 1 < LL) ? s[nt][3] * scale : -1e30f;
        }

        // row max (rows g and g+8)
        float mt0 = -1e30f, mt1 = -1e30f;
#pragma unroll
        for (int nt = 0; nt < 8; nt++) {
            mt0 = fmaxf(mt0, fmaxf(s[nt][0], s[nt][1]));
            mt1 = fmaxf(mt1, fmaxf(s[nt][2], s[nt][3]));
        }
        mt0 = fmaxf(mt0, __shfl_xor_sync(0xffffffffu, mt0, 1));
        mt0 = fmaxf(mt0, __shfl_xor_sync(0xffffffffu, mt0, 2));
        mt1 = fmaxf(mt1, __shfl_xor_sync(0xffffffffu, mt1, 1));
        mt1 = fmaxf(mt1, __shfl_xor_sync(0xffffffffu, mt1, 2));

        float mn0 = fmaxf(m0v, mt0), mn1 = fmaxf(m1v, mt1);
        float al0 = expf(m0v - mn0), al1 = expf(m1v - mn1);
        m0v = mn0; m1v = mn1;

        float rs0 = 0.f, rs1 = 0.f;
#pragma unroll
        for (int nt = 0; nt < 8; nt++) {
            float p0 = expf(s[nt][0] - mn0);
            float p1 = expf(s[nt][1] - mn0);
            float p2 = expf(s[nt][2] - mn1);
            float p3 = expf(s[nt][3] - mn1);
            rs0 += p0 + p1; rs1 += p2 + p3;
            int col = nt * 8 + 2 * tig;
            Ps[mrow + g    ][col] = f2tf32(p0); Ps[mrow + g    ][col + 1] = f2tf32(p1);
            Ps[mrow + g + 8][col] = f2tf32(p2); Ps[mrow + g + 8][col + 1] = f2tf32(p3);
        }
        rs0 += __shfl_xor_sync(0xffffffffu, rs0, 1);
        rs0 += __shfl_xor_sync(0xffffffffu, rs0, 2);
        rs1 += __shfl_xor_sync(0xffffffffu, rs1, 1);
        rs1 += __shfl_xor_sync(0xffffffffu, rs1, 2);
        l0 = l0 * al0 + rs0;
        l1 = l1 * al1 + rs1;

#pragma unroll
        for (int nt = 0; nt < 12; nt++) {
            O[nt][0] *= al0; O[nt][1] *= al0;
            O[nt][2] *= al1; O[nt][3] *= al1;
        }
        __syncwarp();

        // ---- O += P @ V (warp reads only its own 16 P rows) ----
#pragma unroll
        for (int ks = 0; ks < 8; ks++) {
            unsigned pa0 = uldf(&Ps[mrow + g    ][ks * 8 + tig    ]);
            unsigned pa1 = uldf(&Ps[mrow + g + 8][ks * 8 + tig    ]);
            unsigned pa2 = uldf(&Ps[mrow + g    ][ks * 8 + tig + 4]);
            unsigned pa3 = uldf(&Ps[mrow + g + 8][ks * 8 + tig + 4]);
#pragma unroll
            for (int nt = 0; nt < 12; nt++) {
                unsigned b0 = uldf(&Vs[ks * 8 + tig    ][nt * 8 + g]);
                unsigned b1 = uldf(&Vs[ks * 8 + tig + 4][nt * 8 + g]);
                mma_tf32(O[nt], pa0, pa1, pa2, pa3, b0, b1);
            }
        }
    }

    // ---- write out ----
    float inv0 = 1.0f / l0, inv1 = 1.0f / l1;
    int qg0 = qt * 64 + mrow + g;
    int qg1 = qg0 + 8;
    size_t base0 = ((size_t)(b * LL + qg0)) * HH + h * HDD;
    size_t base1 = ((size_t)(b * LL + qg1)) * HH + h * HDD;
#pragma unroll
    for (int nt = 0; nt < 12; nt++) {
        int d0 = nt * 8 + 2 * tig;
        if (qg0 < LL) {
            g_ctx[base0 + d0]     = O[nt][0] * inv0;
            g_ctx[base0 + d0 + 1] = O[nt][1] * inv0;
        }
        if (qg1 < LL) {
            g_ctx[base1 + d0]     = O[nt][2] * inv1;
            g_ctx[base1 + d0 + 1] = O[nt][3] * inv1;
        }
    }
}

// ---------------- finalize: mu/var -> g, C0 --------------------------------
__global__ void finalize_kernel(const float* __restrict__ gamma,
                                const float* __restrict__ beta,
                                const float* __restrict__ w_out,
                                const float* __restrict__ b_out)
{
    __shared__ float red[HH];
    int h = threadIdx.x;
    const double N = (double)NROWS;
    double mu  = g_chsum[h] / N;
    double var = g_chsumsq[h] / N - mu * mu;
    double inv = 1.0 / sqrt(var + 1e-5);
    float g = w_out[h] * gamma[h] * (float)inv;
    g_g[h] = g;
    red[h] = w_out[h] * beta[h] - g * (float)mu;
    __syncthreads();
    if (h < 256) red[h] += red[h + 512];
    __syncthreads();
    for (int s = 256; s > 0; s >>= 1) {
        if (h < s) red[h] += red[h + s];
        __syncthreads();
    }
    if (h == 0) g_c0 = red[0] + b_out[0];
}

// ---------------- fv = c . w_out + attn_out . g + C0 -----------------------
__global__ __launch_bounds__(256) void fv_kernel(const float* __restrict__ cols,
                                                 const float* __restrict__ w_out)
{
    int warp = (blockIdx.x * 256 + threadIdx.x) >> 5;
    int lane = threadIdx.x & 31;
    if (warp >= NROWS) return;
    int b = warp / LL, l = warp % LL;
    const float* crow = cols + ((size_t)(b * SS) + l + 1) * HH;
    const float* arow = g_ao + (size_t)warp * HH;
    float s = 0.f;
    for (int k = lane; k < HH; k += 32)
        s += crow[k] * w_out[k] + arow[k] * g_g[k];
#pragma unroll
    for (int o = 16; o > 0; o >>= 1) s += __shfl_xor_sync(0xffffffffu, s, o);
    if (lane == 0) g_fv[warp] = s + g_c0;
}

// ---------------- segment pooling -------------------------------------------
__global__ void segpool_kernel(const int* __restrict__ ids, float* __restrict__ out, int nseg)
{
    int b = blockIdx.x;
    __shared__ int sc[512];
    __shared__ float ssum[32];
    __shared__ float scnt[32];
    int l = threadIdx.x;  // 0..511
    int ic = 0;
    if (l < LL) ic = (ids[b * SS + l] == COMMA_ID) ? 1 : 0;
    sc[l] = ic;
    __syncthreads();
    for (int off = 1; off < 512; off <<= 1) {
        int v = (l >= off) ? sc[l - off] : 0;
        __syncthreads();
        sc[l] += v;
        __syncthreads();
    }
    int seg = sc[l] - ic;
    if (l < 32) { ssum[l] = 0.f; scnt[l] = 0.f; }
    __syncthreads();
    if (l >= 1 && l < LL && !ic && seg < nseg) {
        atomicAdd(&ssum[seg], g_fv[(size_t)b * LL + l]);
        atomicAdd(&scnt[seg], 1.0f);
    }
    __syncthreads();
    if (l < nseg) out[b * nseg + l] = ssum[l] / fmaxf(scnt[l], 1.0f);
}

// ---------------- launch -----------------------------------------------------
extern "C" void kernel_launch(void* const* d_in, const int* in_sizes, int n_in,
                              void* d_out, int out_size)
{
    const float* text   = (const float*)d_in[0];
    const float* cols   = (const float*)d_in[1];
    const float* wq     = (const float*)d_in[2];
    const float* wk     = (const float*)d_in[3];
    const float* wv     = (const float*)d_in[4];
    const float* bq     = (const float*)d_in[5];
    const float* bk     = (const float*)d_in[6];
    const float* bv     = (const float*)d_in[7];
    const float* wo     = (const float*)d_in[8];
    const float* bo     = (const float*)d_in[9];
    const float* gamma  = (const float*)d_in[10];
    const float* beta   = (const float*)d_in[11];
    const float* w_out  = (const float*)d_in[12];
    const float* b_out  = (const float*)d_in[13];
    const int*   ids    = (const int*)d_in[14];
    float* out = (float*)d_out;
    int nseg = out_size / BB;   // 17

    static int attn_smem_set = 0;
    if (!attn_smem_set) {
        cudaFuncSetAttribute(attn_kernel,
            cudaFuncAttributeMaxDynamicSharedMemorySize, ATTN_SMEM);
        attn_smem_set = 1;
    }

    zero_stats_kernel<<<1, HH>>>();
    qkv_gemm_kernel<<<dim3(256, 18), 256>>>(text, cols, wq, wk, wv, bq, bk, bv);
    attn_kernel<<<dim3(8, 512), 128, ATTN_SMEM>>>();
    wo_gemm_kernel<<<dim3(256, 6), 256>>>(wo, bo);
    finalize_kernel<<<1, HH>>>(gamma, beta, w_out, b_out);
    fv_kernel<<<(NROWS + 7) / 8, 256>>>(cols, w_out);
    segpool_kernel<<<BB, 512>>>(ids, out, nseg);
}

// round 3
// speedup vs baseline: 3.2270x; 1.2515x over previous
#include <cuda_runtime.h>
#include <math.h>
#include <stdint.h>

#define HH 768
#define NHD 8
#define HDD 96
#define BB 64
#define SS 512
#define LL 511
#define NROWS (BB*LL)          // 32704
#define BUF_ELEMS (NROWS*HH)   // 25116672
#define COMMA_ID 1010

// ---------------- scratch (device globals; no allocation allowed) ----------
static __device__ float g_q[BUF_ELEMS];      // [b][h][l][d]
static __device__ float g_k[BUF_ELEMS];
static __device__ float g_v[BUF_ELEMS];
static __device__ float g_ctx[BUF_ELEMS];    // [row=b*511+l][H]
static __device__ float g_ao[BUF_ELEMS];     // attn_out, same layout as ctx
static __device__ float g_fv[NROWS];
static __device__ double g_chsum[HH];
static __device__ double g_chsumsq[HH];
static __device__ float g_g[HH];
static __device__ float g_c0;

// ---------------- tf32 / mma / ldmatrix helpers ----------------
__device__ __forceinline__ float f2tf32(float x) {
    unsigned r;
    asm("cvt.rna.tf32.f32 %0, %1;" : "=r"(r) : "f"(x));
    return __uint_as_float(r);
}
__device__ __forceinline__ unsigned uldf(const float* p) {
    return __float_as_uint(*p);
}
__device__ __forceinline__ void mma_tf32(float c[4],
    unsigned a0, unsigned a1, unsigned a2, unsigned a3,
    unsigned b0, unsigned b1)
{
    asm volatile(
        "mma.sync.aligned.m16n8k8.row.col.f32.tf32.tf32.f32 "
        "{%0,%1,%2,%3}, {%4,%5,%6,%7}, {%8,%9}, {%0,%1,%2,%3};"
        : "+f"(c[0]), "+f"(c[1]), "+f"(c[2]), "+f"(c[3])
        : "r"(a0), "r"(a1), "r"(a2), "r"(a3), "r"(b0), "r"(b1));
}
__device__ __forceinline__ void ldsm4(unsigned &r0, unsigned &r1,
                                      unsigned &r2, unsigned &r3, uint32_t addr)
{
    asm volatile("ldmatrix.sync.aligned.m8n8.x4.shared.b16 {%0,%1,%2,%3}, [%4];"
        : "=r"(r0), "=r"(r1), "=r"(r2), "=r"(r3) : "r"(addr));
}

// ---------------- zero stats ----------------
__global__ void zero_stats_kernel() {
    int i = threadIdx.x;
    if (i < HH) { g_chsum[i] = 0.0; g_chsumsq[i] = 0.0; }
}

// ============================================================================
// TF32 tensor-core GEMM, ldmatrix + double-buffered smem.
// C[M, 768] = A @ W^T + bias. BM=128, BN=128, BK=32, 256 threads (8 warps 2x4),
// warp tile 64x32 (4x4 m16n8k8).
// Smem: A as [m][k] (swizzled), B as [n][k] (swizzled); 2 buffers each.
//   byte offset of (row, kgranule kg): row*128 + ((kg ^ (row&7))*16)
// Regions: A buf c at c*16384; B buf c at 32768 + c*16384. Total 64 KB.
// ============================================================================
#define GEMM_SMEM 65536

__device__ __forceinline__ void gemm_compute(
    uint32_t sm_u, int cur, int mbase, int nbase, int lane, float acc[4][4][4])
{
    int lane_r = (lane & 7) + ((lane >> 3) & 1) * 8;
    int sel = lane >> 4;          // 0/1: low/high k half
    int sw  = lane & 7;
    uint32_t abase = sm_u + (uint32_t)(cur * 16384) + (uint32_t)((mbase + lane_r) * 128);
    uint32_t bbase = sm_u + 32768u + (uint32_t)(cur * 16384) + (uint32_t)((nbase + lane_r) * 128);
#pragma unroll
    for (int ks = 0; ks < 4; ks++) {
        uint32_t kgo = (uint32_t)((((2 * ks + sel) ^ sw)) * 16);
        unsigned a[4][4];
#pragma unroll
        for (int mt = 0; mt < 4; mt++)
            ldsm4(a[mt][0], a[mt][1], a[mt][2], a[mt][3], abase + mt * 2048 + kgo);
        unsigned blo[4], bhi[4];
#pragma unroll
        for (int ntp = 0; ntp < 2; ntp++) {
            unsigned r0, r1, r2, r3;
            ldsm4(r0, r1, r2, r3, bbase + ntp * 2048 + kgo);
            blo[2 * ntp] = r0; blo[2 * ntp + 1] = r1;
            bhi[2 * ntp] = r2; bhi[2 * ntp + 1] = r3;
        }
#pragma unroll
        for (int mt = 0; mt < 4; mt++)
#pragma unroll
            for (int nt = 0; nt < 4; nt++)
                mma_tf32(acc[mt][nt], a[mt][0], a[mt][1], a[mt][2], a[mt][3],
                         blo[nt], bhi[nt]);
    }
}

#define GEMM_PROLOG() \
    int tid  = threadIdx.x; \
    int lane = tid & 31, warp = tid >> 5; \
    int g = lane >> 2, tig = lane & 3; \
    int mbase = (warp >> 2) * 64, nbase = (warp & 3) * 32; \
    int m0 = blockIdx.x * 128; \
    extern __shared__ float smf[]; \
    char* smc = (char*)smf; \
    uint32_t sm_u = (uint32_t)__cvta_generic_to_shared(smf); \
    int r0i = tid >> 3; \
    int kg  = tid & 7; \
    int swsts = ((kg ^ (r0i & 7)) * 16); \
    int stsOff[4]; \
    _Pragma("unroll") for (int u = 0; u < 4; u++) \
        stsOff[u] = (r0i + u * 32) * 128 + swsts; \
    float acc[4][4][4]; \
    _Pragma("unroll") for (int a = 0; a < 4; a++) \
    _Pragma("unroll") for (int b = 0; b < 4; b++) \
    _Pragma("unroll") for (int c = 0; c < 4; c++) acc[a][b][c] = 0.f;

#define GEMM_LOAD(k0) \
    _Pragma("unroll") for (int u = 0; u < 4; u++) { \
        ra[u] = *(const float4*)(arowp[u] + (k0)); \
        rb[u] = *(const float4*)(wrowp[u] + (k0)); \
    }

#define GEMM_STORE(buf) \
    _Pragma("unroll") for (int u = 0; u < 4; u++) { \
        float4 ca, cb; \
        ca.x = f2tf32(ra[u].x); ca.y = f2tf32(ra[u].y); \
        ca.z = f2tf32(ra[u].z); ca.w = f2tf32(ra[u].w); \
        cb.x = f2tf32(rb[u].x); cb.y = f2tf32(rb[u].y); \
        cb.z = f2tf32(rb[u].z); cb.w = f2tf32(rb[u].w); \
        *(float4*)(smc + (buf) * 16384 + stsOff[u]) = ca; \
        *(float4*)(smc + 32768 + (buf) * 16384 + stsOff[u]) = cb; \
    }

#define GEMM_MAINLOOP() \
    float4 ra[4], rb[4]; \
    GEMM_LOAD(0); \
    GEMM_STORE(0); \
    __syncthreads(); \
    for (int it = 0; it < 24; it++) { \
        int cur = it & 1; \
        if (it < 23) { GEMM_LOAD((it + 1) * 32); } \
        gemm_compute(sm_u, cur, mbase, nbase, lane, acc); \
        if (it < 23) { GEMM_STORE(cur ^ 1); } \
        __syncthreads(); \
    }

// ---- QKV GEMM: grid (256, 18) ----
__global__ __launch_bounds__(256, 2) void qkv_gemm_kernel(
    const float* __restrict__ text, const float* __restrict__ cols,
    const float* __restrict__ wq, const float* __restrict__ wk, const float* __restrict__ wv,
    const float* __restrict__ bq, const float* __restrict__ bk, const float* __restrict__ bv)
{
    GEMM_PROLOG();

    int nt_blk = blockIdx.y;
    int sec = nt_blk / 6;
    int nb  = (nt_blk % 6) * 128;
    const float* A    = (sec == 0) ? cols : text;
    const float* W    = (sec == 0) ? wq : (sec == 1 ? wk : wv);
    const float* bias = (sec == 0) ? bq : (sec == 1 ? bk : bv);
    float* out        = (sec == 0) ? g_q : (sec == 1 ? g_k : g_v);

    const float* arowp[4];
    const float* wrowp[4];
#pragma unroll
    for (int u = 0; u < 4; u++) {
        int row = m0 + r0i + u * 32;
        if (row >= NROWS) row = 0;
        int b = row / LL, l = row % LL;
        arowp[u] = A + ((size_t)(b * SS + l + 1)) * HH + kg * 4;
        wrowp[u] = W + (size_t)(nb + r0i + u * 32) * HH + kg * 4;
    }

    GEMM_MAINLOOP();

    // epilogue -> [b][h][l][d]
#pragma unroll
    for (int mt = 0; mt < 4; mt++) {
        int row0 = m0 + mbase + mt * 16 + g;
        int row1 = row0 + 8;
#pragma unroll
        for (int nt = 0; nt < 4; nt++) {
            int col0 = nb + nbase + nt * 8 + 2 * tig;
            float bi0 = bias[col0], bi1 = bias[col0 + 1];
            int h0 = col0 / HDD, d0 = col0 % HDD;
            int h1 = (col0 + 1) / HDD, d1 = (col0 + 1) % HDD;
            if (row0 < NROWS) {
                int b = row0 / LL, l = row0 % LL;
                out[(((size_t)(b * NHD + h0)) * LL + l) * HDD + d0] = acc[mt][nt][0] + bi0;
                out[(((size_t)(b * NHD + h1)) * LL + l) * HDD + d1] = acc[mt][nt][1] + bi1;
            }
            if (row1 < NROWS) {
                int b = row1 / LL, l = row1 % LL;
                out[(((size_t)(b * NHD + h0)) * LL + l) * HDD + d0] = acc[mt][nt][2] + bi0;
                out[(((size_t)(b * NHD + h1)) * LL + l) * HDD + d1] = acc[mt][nt][3] + bi1;
            }
        }
    }
}

// ---- wo GEMM + per-channel stats: grid (256, 6) ----
__global__ __launch_bounds__(256, 2) void wo_gemm_kernel(
    const float* __restrict__ wo, const float* __restrict__ bo)
{
    GEMM_PROLOG();

    int nb = blockIdx.y * 128;
    __shared__ float scol[128];
    __shared__ float scolq[128];
    if (tid < 128) { scol[tid] = 0.f; scolq[tid] = 0.f; }

    const float* arowp[4];
    const float* wrowp[4];
#pragma unroll
    for (int u = 0; u < 4; u++) {
        int row = m0 + r0i + u * 32;
        if (row >= NROWS) row = 0;
        arowp[u] = g_ctx + (size_t)row * HH + kg * 4;
        wrowp[u] = wo + (size_t)(nb + r0i + u * 32) * HH + kg * 4;
    }

    GEMM_MAINLOOP();

#pragma unroll
    for (int nt = 0; nt < 4; nt++) {
        int nl0 = nbase + nt * 8 + 2 * tig;
        int n0 = nb + nl0;
        float bi0 = bo[n0], bi1 = bo[n0 + 1];
        float s0 = 0.f, q0 = 0.f, s1 = 0.f, q1 = 0.f;
#pragma unroll
        for (int mt = 0; mt < 4; mt++) {
            int row0 = m0 + mbase + mt * 16 + g;
            int row1 = row0 + 8;
            if (row0 < NROWS) {
                float v0 = acc[mt][nt][0] + bi0;
                float v1 = acc[mt][nt][1] + bi1;
                g_ao[(size_t)row0 * HH + n0]     = v0;
                g_ao[(size_t)row0 * HH + n0 + 1] = v1;
                s0 += v0; q0 += v0 * v0; s1 += v1; q1 += v1 * v1;
            }
            if (row1 < NROWS) {
                float v0 = acc[mt][nt][2] + bi0;
                float v1 = acc[mt][nt][3] + bi1;
                g_ao[(size_t)row1 * HH + n0]     = v0;
                g_ao[(size_t)row1 * HH + n0 + 1] = v1;
                s0 += v0; q0 += v0 * v0; s1 += v1; q1 += v1 * v1;
            }
        }
        atomicAdd(&scol[nl0], s0);      atomicAdd(&scolq[nl0], q0);
        atomicAdd(&scol[nl0 + 1], s1);  atomicAdd(&scolq[nl0 + 1], q1);
    }
    __syncthreads();
    if (tid < 128) {
        atomicAdd(&g_chsum[nb + tid], (double)scol[tid]);
        atomicAdd(&g_chsumsq[nb + tid], (double)scolq[tid]);
    }
}

// ============================================================================
// TF32 MMA flash attention (unchanged from R2).
// ============================================================================
#define KS_LD 100
#define VS_LD 104
#define PS_LD 68
#define ATTN_SMEM ((64*KS_LD + 64*VS_LD + 64*PS_LD) * 4)

__global__ __launch_bounds__(128) void attn_kernel()
{
    extern __shared__ float sm[];
    float (*Ks)[KS_LD] = (float (*)[KS_LD])sm;
    float (*Vs)[VS_LD] = (float (*)[VS_LD])(sm + 64 * KS_LD);
    float (*Ps)[PS_LD] = (float (*)[PS_LD])(sm + 64 * KS_LD + 64 * VS_LD);

    int qt = blockIdx.x;
    int bh = blockIdx.y;
    int b = bh >> 3, h = bh & 7;
    const float* Q = g_q + (size_t)bh * LL * HDD;
    const float* K = g_k + (size_t)bh * LL * HDD;
    const float* V = g_v + (size_t)bh * LL * HDD;

    int tid  = threadIdx.x;
    int lane = tid & 31, warp = tid >> 5;
    int g = lane >> 2, tig = lane & 3;
    int mrow = warp * 16;

    for (int idx = tid; idx < 64 * 24; idx += 128) {
        int r = idx / 24, c = (idx % 24) * 4;
        int qg = qt * 64 + r; if (qg > LL - 1) qg = LL - 1;
        float4 v = *(const float4*)(Q + (size_t)qg * HDD + c);
        Ks[r][c + 0] = f2tf32(v.x); Ks[r][c + 1] = f2tf32(v.y);
        Ks[r][c + 2] = f2tf32(v.z); Ks[r][c + 3] = f2tf32(v.w);
    }
    __syncthreads();

    unsigned qa[12][4];
#pragma unroll
    for (int ks = 0; ks < 12; ks++) {
        qa[ks][0] = uldf(&Ks[mrow + g    ][ks * 8 + tig    ]);
        qa[ks][1] = uldf(&Ks[mrow + g + 8][ks * 8 + tig    ]);
        qa[ks][2] = uldf(&Ks[mrow + g    ][ks * 8 + tig + 4]);
        qa[ks][3] = uldf(&Ks[mrow + g + 8][ks * 8 + tig + 4]);
    }

    float O[12][4];
#pragma unroll
    for (int nt = 0; nt < 12; nt++)
#pragma unroll
        for (int c = 0; c < 4; c++) O[nt][c] = 0.f;
    float m0v = -1e30f, m1v = -1e30f, l0 = 0.f, l1 = 0.f;

    const float scale = 0.10206207261596575f;

    for (int kt = 0; kt < 8; kt++) {
        int ktb = kt * 64;
        __syncthreads();
        for (int idx = tid; idx < 64 * 24; idx += 128) {
            int r = idx / 24, c = (idx % 24) * 4;
            int kg2 = ktb + r;
            if (kg2 < LL) {
                float4 kv = *(const float4*)(K + (size_t)kg2 * HDD + c);
                float4 vv = *(const float4*)(V + (size_t)kg2 * HDD + c);
                Ks[r][c+0]=f2tf32(kv.x); Ks[r][c+1]=f2tf32(kv.y);
                Ks[r][c+2]=f2tf32(kv.z); Ks[r][c+3]=f2tf32(kv.w);
                Vs[r][c+0]=f2tf32(vv.x); Vs[r][c+1]=f2tf32(vv.y);
                Vs[r][c+2]=f2tf32(vv.z); Vs[r][c+3]=f2tf32(vv.w);
            } else {
                Ks[r][c+0]=0.f; Ks[r][c+1]=0.f; Ks[r][c+2]=0.f; Ks[r][c+3]=0.f;
                Vs[r][c+0]=0.f; Vs[r][c+1]=0.f; Vs[r][c+2]=0.f; Vs[r][c+3]=0.f;
            }
        }
        __syncthreads();

        float s[8][4];
#pragma unroll
        for (int nt = 0; nt < 8; nt++)
#pragma unroll
            for (int c = 0; c < 4; c++) s[nt][c] = 0.f;

#pragma unroll
        for (int ks = 0; ks < 12; ks++) {
#pragma unroll
            for (int nt = 0; nt < 8; nt++) {
                unsigned b0 = uldf(&Ks[nt * 8 + g][ks * 8 + tig    ]);
                unsigned b1 = uldf(&Ks[nt * 8 + g][ks * 8 + tig + 4]);
                mma_tf32(s[nt], qa[ks][0], qa[ks][1], qa[ks][2], qa[ks][3], b0, b1);
            }
        }

#pragma unroll
        for (int nt = 0; nt < 8; nt++) {
            int col = ktb + nt * 8 + 2 * tig;
            s[nt][0] = (col     < LL) ? s[nt][0] * scale : -1e30f;
            s[nt][1] = (col + 1 < LL) ? s[nt][1] * scale : -1e30f;
            s[nt][2] = (col     < LL) ? s[nt][2] * scale : -1e30f;
            s[nt][3] = (col + 1 < LL) ? s[nt][3] * scale : -1e30f;
        }

        float mt0 = -1e30f, mt1 = -1e30f;
#pragma unroll
        for (int nt = 0; nt < 8; nt++) {
            mt0 = fmaxf(mt0, fmaxf(s[nt][0], s[nt][1]));
            mt1 = fmaxf(mt1, fmaxf(s[nt][2], s[nt][3]));
        }
        mt0 = fmaxf(mt0, __shfl_xor_sync(0xffffffffu, mt0, 1));
        mt0 = fmaxf(mt0, __shfl_xor_sync(0xffffffffu, mt0, 2));
        mt1 = fmaxf(mt1, __shfl_xor_sync(0xffffffffu, mt1, 1));
        mt1 = fmaxf(mt1, __shfl_xor_sync(0xffffffffu, mt1, 2));

        float mn0 = fmaxf(m0v, mt0), mn1 = fmaxf(m1v, mt1);
        float al0 = expf(m0v - mn0), al1 = expf(m1v - mn1);
        m0v = mn0; m1v = mn1;

        float rs0 = 0.f, rs1 = 0.f;
#pragma unroll
        for (int nt = 0; nt < 8; nt++) {
            float p0 = expf(s[nt][0] - mn0);
            float p1 = expf(s[nt][1] - mn0);
            float p2 = expf(s[nt][2] - mn1);
            float p3 = expf(s[nt][3] - mn1);
            rs0 += p0 + p1; rs1 += p2 + p3;
            int col = nt * 8 + 2 * tig;
            Ps[mrow + g    ][col] = f2tf32(p0); Ps[mrow + g    ][col + 1] = f2tf32(p1);
            Ps[mrow + g + 8][col] = f2tf32(p2); Ps[mrow + g + 8][col + 1] = f2tf32(p3);
        }
        rs0 += __shfl_xor_sync(0xffffffffu, rs0, 1);
        rs0 += __shfl_xor_sync(0xffffffffu, rs0, 2);
        rs1 += __shfl_xor_sync(0xffffffffu, rs1, 1);
        rs1 += __shfl_xor_sync(0xffffffffu, rs1, 2);
        l0 = l0 * al0 + rs0;
        l1 = l1 * al1 + rs1;

#pragma unroll
        for (int nt = 0; nt < 12; nt++) {
            O[nt][0] *= al0; O[nt][1] *= al0;
            O[nt][2] *= al1; O[nt][3] *= al1;
        }
        __syncwarp();

#pragma unroll
        for (int ks = 0; ks < 8; ks++) {
            unsigned pa0 = uldf(&Ps[mrow + g    ][ks * 8 + tig    ]);
            unsigned pa1 = uldf(&Ps[mrow + g + 8][ks * 8 + tig    ]);
            unsigned pa2 = uldf(&Ps[mrow + g    ][ks * 8 + tig + 4]);
            unsigned pa3 = uldf(&Ps[mrow + g + 8][ks * 8 + tig + 4]);
#pragma unroll
            for (int nt = 0; nt < 12; nt++) {
                unsigned b0 = uldf(&Vs[ks * 8 + tig    ][nt * 8 + g]);
                unsigned b1 = uldf(&Vs[ks * 8 + tig + 4][nt * 8 + g]);
                mma_tf32(O[nt], pa0, pa1, pa2, pa3, b0, b1);
            }
        }
    }

    float inv0 = 1.0f / l0, inv1 = 1.0f / l1;
    int qg0 = qt * 64 + mrow + g;
    int qg1 = qg0 + 8;
    size_t base0 = ((size_t)(b * LL + qg0)) * HH + h * HDD;
    size_t base1 = ((size_t)(b * LL + qg1)) * HH + h * HDD;
#pragma unroll
    for (int nt = 0; nt < 12; nt++) {
        int d0 = nt * 8 + 2 * tig;
        if (qg0 < LL) {
            g_ctx[base0 + d0]     = O[nt][0] * inv0;
            g_ctx[base0 + d0 + 1] = O[nt][1] * inv0;
        }
        if (qg1 < LL) {
            g_ctx[base1 + d0]     = O[nt][2] * inv1;
            g_ctx[base1 + d0 + 1] = O[nt][3] * inv1;
        }
    }
}

// ---------------- finalize: mu/var -> g, C0 --------------------------------
__global__ void finalize_kernel(const float* __restrict__ gamma,
                                const float* __restrict__ beta,
                                const float* __restrict__ w_out,
                                const float* __restrict__ b_out)
{
    __shared__ float red[HH];
    int h = threadIdx.x;
    const double N = (double)NROWS;
    double mu  = g_chsum[h] / N;
    double var = g_chsumsq[h] / N - mu * mu;
    double inv = 1.0 / sqrt(var + 1e-5);
    float g = w_out[h] * gamma[h] * (float)inv;
    g_g[h] = g;
    red[h] = w_out[h] * beta[h] - g * (float)mu;
    __syncthreads();
    if (h < 256) red[h] += red[h + 512];
    __syncthreads();
    for (int s = 256; s > 0; s >>= 1) {
        if (h < s) red[h] += red[h + s];
        __syncthreads();
    }
    if (h == 0) g_c0 = red[0] + b_out[0];
}

// ---------------- fv = c . w_out + attn_out . g + C0 -----------------------
__global__ __launch_bounds__(256) void fv_kernel(const float* __restrict__ cols,
                                                 const float* __restrict__ w_out)
{
    int warp = (blockIdx.x * 256 + threadIdx.x) >> 5;
    int lane = threadIdx.x & 31;
    if (warp >= NROWS) return;
    int b = warp / LL, l = warp % LL;
    const float* crow = cols + ((size_t)(b * SS) + l + 1) * HH;
    const float* arow = g_ao + (size_t)warp * HH;
    float s = 0.f;
    for (int k = lane; k < HH; k += 32)
        s += crow[k] * w_out[k] + arow[k] * g_g[k];
#pragma unroll
    for (int o = 16; o > 0; o >>= 1) s += __shfl_xor_sync(0xffffffffu, s, o);
    if (lane == 0) g_fv[warp] = s + g_c0;
}

// ---------------- segment pooling -------------------------------------------
__global__ void segpool_kernel(const int* __restrict__ ids, float* __restrict__ out, int nseg)
{
    int b = blockIdx.x;
    __shared__ int sc[512];
    __shared__ float ssum[32];
    __shared__ float scnt[32];
    int l = threadIdx.x;
    int ic = 0;
    if (l < LL) ic = (ids[b * SS + l] == COMMA_ID) ? 1 : 0;
    sc[l] = ic;
    __syncthreads();
    for (int off = 1; off < 512; off <<= 1) {
        int v = (l >= off) ? sc[l - off] : 0;
        __syncthreads();
        sc[l] += v;
        __syncthreads();
    }
    int seg = sc[l] - ic;
    if (l < 32) { ssum[l] = 0.f; scnt[l] = 0.f; }
    __syncthreads();
    if (l >= 1 && l < LL && !ic && seg < nseg) {
        atomicAdd(&ssum[seg], g_fv[(size_t)b * LL + l]);
        atomicAdd(&scnt[seg], 1.0f);
    }
    __syncthreads();
    if (l < nseg) out[b * nseg + l] = ssum[l] / fmaxf(scnt[l], 1.0f);
}

// ---------------- launch -----------------------------------------------------
extern "C" void kernel_launch(void* const* d_in, const int* in_sizes, int n_in,
                              void* d_out, int out_size)
{
    const float* text   = (const float*)d_in[0];
    const float* cols   = (const float*)d_in[1];
    const float* wq     = (const float*)d_in[2];
    const float* wk     = (const float*)d_in[3];
    const float* wv     = (const float*)d_in[4];
    const float* bq     = (const float*)d_in[5];
    const float* bk     = (const float*)d_in[6];
    const float* bv     = (const float*)d_in[7];
    const float* wo     = (const float*)d_in[8];
    const float* bo     = (const float*)d_in[9];
    const float* gamma  = (const float*)d_in[10];
    const float* beta   = (const float*)d_in[11];
    const float* w_out  = (const float*)d_in[12];
    const float* b_out  = (const float*)d_in[13];
    const int*   ids    = (const int*)d_in[14];
    float* out = (float*)d_out;
    int nseg = out_size / BB;   // 17

    static int attrs_set = 0;
    if (!attrs_set) {
        cudaFuncSetAttribute(attn_kernel,
            cudaFuncAttributeMaxDynamicSharedMemorySize, ATTN_SMEM);
        cudaFuncSetAttribute(qkv_gemm_kernel,
            cudaFuncAttributeMaxDynamicSharedMemorySize, GEMM_SMEM);
        cudaFuncSetAttribute(wo_gemm_kernel,
            cudaFuncAttributeMaxDynamicSharedMemorySize, GEMM_SMEM);
        attrs_set = 1;
    }

    zero_stats_kernel<<<1, HH>>>();
    qkv_gemm_kernel<<<dim3(256, 18), 256, GEMM_SMEM>>>(text, cols, wq, wk, wv, bq, bk, bv);
    attn_kernel<<<dim3(8, 512), 128, ATTN_SMEM>>>();
    wo_gemm_kernel<<<dim3(256, 6), 256, GEMM_SMEM>>>(wo, bo);
    finalize_kernel<<<1, HH>>>(gamma, beta, w_out, b_out);
    fv_kernel<<<(NROWS + 7) / 8, 256>>>(cols, w_out);
    segpool_kernel<<<BB, 512>>>(ids, out, nseg);
}

// round 4
// speedup vs baseline: 4.6036x; 1.4266x over previous
#include <cuda_runtime.h>
#include <math.h>
#include <stdint.h>

#define HH 768
#define NHD 8
#define HDD 96
#define BB 64
#define SS 512
#define LL 511
#define NROWS (BB*LL)          // 32704
#define BUF_ELEMS (NROWS*HH)   // 25116672
#define COMMA_ID 1010
#define WELEMS (HH*HH)         // 589824

// ---------------- scratch (device globals; no allocation allowed) ----------
static __device__ float g_q[BUF_ELEMS];      // [b][h][l][d] (tf32-rounded)
static __device__ float g_k[BUF_ELEMS];
static __device__ float g_v[BUF_ELEMS];
static __device__ float g_ctx[BUF_ELEMS];    // [row][H] (tf32-rounded)
static __device__ float g_ao[BUF_ELEMS];     // attn_out fp32
static __device__ float g_textc[BUF_ELEMS];  // pre-converted, row-shifted
static __device__ float g_colsc[BUF_ELEMS];
static __device__ float g_wc[4 * WELEMS];    // q,k,v,o tf32-rounded weights
static __device__ float g_fv[NROWS];
static __device__ double g_chsum[HH];
static __device__ double g_chsumsq[HH];
static __device__ float g_g[HH];
static __device__ float g_c0;

// ---------------- tf32 / mma / ldmatrix / cp.async helpers ----------------
__device__ __forceinline__ float f2tf32(float x) {
    unsigned r;
    asm("cvt.rna.tf32.f32 %0, %1;" : "=r"(r) : "f"(x));
    return __uint_as_float(r);
}
__device__ __forceinline__ unsigned uldf(const float* p) {
    return __float_as_uint(*p);
}
__device__ __forceinline__ void mma_tf32(float c[4],
    unsigned a0, unsigned a1, unsigned a2, unsigned a3,
    unsigned b0, unsigned b1)
{
    asm volatile(
        "mma.sync.aligned.m16n8k8.row.col.f32.tf32.tf32.f32 "
        "{%0,%1,%2,%3}, {%4,%5,%6,%7}, {%8,%9}, {%0,%1,%2,%3};"
        : "+f"(c[0]), "+f"(c[1]), "+f"(c[2]), "+f"(c[3])
        : "r"(a0), "r"(a1), "r"(a2), "r"(a3), "r"(b0), "r"(b1));
}
__device__ __forceinline__ void ldsm4(unsigned &r0, unsigned &r1,
                                      unsigned &r2, unsigned &r3, uint32_t addr)
{
    asm volatile("ldmatrix.sync.aligned.m8n8.x4.shared.b16 {%0,%1,%2,%3}, [%4];"
        : "=r"(r0), "=r"(r1), "=r"(r2), "=r"(r3) : "r"(addr));
}
__device__ __forceinline__ void cpa16(uint32_t dst, const float* src) {
    asm volatile("cp.async.cg.shared.global [%0], [%1], 16;" :: "r"(dst), "l"(src));
}
__device__ __forceinline__ void cpa16z(uint32_t dst, const float* src, int sz) {
    asm volatile("cp.async.cg.shared.global [%0], [%1], 16, %2;"
                 :: "r"(dst), "l"(src), "r"(sz));
}

// ---------------- zero stats ----------------
__global__ void zero_stats_kernel() {
    int i = threadIdx.x;
    if (i < HH) { g_chsum[i] = 0.0; g_chsumsq[i] = 0.0; }
}

// ---------------- pre-convert activations (tf32 + row shift) ----------------
__global__ __launch_bounds__(256) void convert_acts_kernel(
    const float* __restrict__ text, const float* __restrict__ cols)
{
    const float* src = blockIdx.y ? cols : text;
    float* dst = blockIdx.y ? g_colsc : g_textc;
    size_t i = (size_t)blockIdx.x * 256 + threadIdx.x;   // float4 index
    if (i >= (size_t)NROWS * 192) return;
    int row = (int)(i / 192), c4 = (int)(i % 192);
    int b = row / LL, l = row % LL;
    float4 v = *(const float4*)(src + ((size_t)(b * SS + l + 1)) * HH + c4 * 4);
    float4 o;
    o.x = f2tf32(v.x); o.y = f2tf32(v.y); o.z = f2tf32(v.z); o.w = f2tf32(v.w);
    *(float4*)(dst + (size_t)row * HH + c4 * 4) = o;
}

// ---------------- pre-convert weights ----------------
__global__ __launch_bounds__(256) void convert_w_kernel(
    const float* __restrict__ wq, const float* __restrict__ wk,
    const float* __restrict__ wv, const float* __restrict__ wo)
{
    int mat = blockIdx.y;
    const float* s = (mat == 0) ? wq : (mat == 1) ? wk : (mat == 2) ? wv : wo;
    size_t i = (size_t)blockIdx.x * 256 + threadIdx.x;   // float4 index
    if (i >= WELEMS / 4) return;
    float4 v = ((const float4*)s)[i];
    float4 o;
    o.x = f2tf32(v.x); o.y = f2tf32(v.y); o.z = f2tf32(v.z); o.w = f2tf32(v.w);
    ((float4*)(g_wc + (size_t)mat * WELEMS))[i] = o;
}

// ============================================================================
// TF32 GEMM: cp.async 3-stage pipeline + ldmatrix + m16n8k8.
// BM=128, BN=128, BK=32, 256 threads (8 warps 2x4), warp tile 64x32.
// Smem byte offset of (row, kgranule kg): row*128 + ((kg ^ (row&7))*16).
// A stage s at s*16384; B stage s at 49152 + s*16384. Total 96 KB.
// ============================================================================
#define GEMM_SMEM 98304

__device__ __forceinline__ void gemm_compute(
    uint32_t sm_u, int cur, int mbase, int nbase, int lane, float acc[4][4][4])
{
    int lane_r = (lane & 7) + ((lane >> 3) & 1) * 8;
    int sel = lane >> 4;
    int sw  = lane & 7;
    uint32_t abase = sm_u + (uint32_t)(cur * 16384) + (uint32_t)((mbase + lane_r) * 128);
    uint32_t bbase = sm_u + 49152u + (uint32_t)(cur * 16384) + (uint32_t)((nbase + lane_r) * 128);
#pragma unroll
    for (int ks = 0; ks < 4; ks++) {
        uint32_t kgo = (uint32_t)((((2 * ks + sel) ^ sw)) * 16);
        unsigned a[4][4];
#pragma unroll
        for (int mt = 0; mt < 4; mt++)
            ldsm4(a[mt][0], a[mt][1], a[mt][2], a[mt][3], abase + mt * 2048 + kgo);
        unsigned blo[4], bhi[4];
#pragma unroll
        for (int ntp = 0; ntp < 2; ntp++) {
            unsigned r0, r1, r2, r3;
            ldsm4(r0, r1, r2, r3, bbase + ntp * 2048 + kgo);
            blo[2 * ntp] = r0; blo[2 * ntp + 1] = r1;
            bhi[2 * ntp] = r2; bhi[2 * ntp + 1] = r3;
        }
#pragma unroll
        for (int mt = 0; mt < 4; mt++)
#pragma unroll
            for (int nt = 0; nt < 4; nt++)
                mma_tf32(acc[mt][nt], a[mt][0], a[mt][1], a[mt][2], a[mt][3],
                         blo[nt], bhi[nt]);
    }
}

#define GEMM_PROLOG() \
    int tid  = threadIdx.x; \
    int lane = tid & 31, warp = tid >> 5; \
    int g = lane >> 2, tig = lane & 3; \
    int mbase = (warp >> 2) * 64, nbase = (warp & 3) * 32; \
    int m0 = blockIdx.x * 128; \
    extern __shared__ float smf[]; \
    uint32_t sm_u = (uint32_t)__cvta_generic_to_shared(smf); \
    int r0i = tid >> 3; \
    int kg  = tid & 7; \
    int swsts = ((kg ^ (r0i & 7)) * 16); \
    int stsOff[4]; \
    _Pragma("unroll") for (int u = 0; u < 4; u++) \
        stsOff[u] = (r0i + u * 32) * 128 + swsts; \
    float acc[4][4][4]; \
    _Pragma("unroll") for (int a = 0; a < 4; a++) \
    _Pragma("unroll") for (int b = 0; b < 4; b++) \
    _Pragma("unroll") for (int c = 0; c < 4; c++) acc[a][b][c] = 0.f;

#define GEMM_ISSUE(stage, k0) do { \
    uint32_t _ab = sm_u + (uint32_t)((stage) * 16384); \
    uint32_t _bb = sm_u + 49152u + (uint32_t)((stage) * 16384); \
    _Pragma("unroll") for (int u = 0; u < 4; u++) { \
        cpa16(_ab + stsOff[u], arowp[u] + (k0)); \
        cpa16(_bb + stsOff[u], wrowp[u] + (k0)); \
    } \
    asm volatile("cp.async.commit_group;"); \
} while (0)

#define GEMM_MAINLOOP() \
    GEMM_ISSUE(0, 0); GEMM_ISSUE(1, 32); GEMM_ISSUE(2, 64); \
    for (int it = 0; it < 24; it++) { \
        int cur = it % 3; \
        asm volatile("cp.async.wait_group 2;"); \
        __syncthreads(); \
        gemm_compute(sm_u, cur, mbase, nbase, lane, acc); \
        __syncthreads(); \
        if (it + 3 < 24) { GEMM_ISSUE(cur, (it + 3) * 32); } \
        else { asm volatile("cp.async.commit_group;"); } \
    }

// ---- QKV GEMM: grid (256, 18) ----
__global__ __launch_bounds__(256, 2) void qkv_gemm_kernel(
    const float* __restrict__ bq, const float* __restrict__ bk, const float* __restrict__ bv)
{
    GEMM_PROLOG();

    int nt_blk = blockIdx.y;
    int sec = nt_blk / 6;
    int nb  = (nt_blk % 6) * 128;
    const float* A    = (sec == 0) ? g_colsc : g_textc;
    const float* W    = g_wc + (size_t)sec * WELEMS;
    const float* bias = (sec == 0) ? bq : (sec == 1 ? bk : bv);
    float* out        = (sec == 0) ? g_q : (sec == 1 ? g_k : g_v);

    const float* arowp[4];
    const float* wrowp[4];
#pragma unroll
    for (int u = 0; u < 4; u++) {
        int row = m0 + r0i + u * 32;
        if (row >= NROWS) row = 0;
        arowp[u] = A + (size_t)row * HH + kg * 4;
        wrowp[u] = W + (size_t)(nb + r0i + u * 32) * HH + kg * 4;
    }

    GEMM_MAINLOOP();

    // epilogue -> [b][h][l][d], tf32-rounded (consumed by attention MMA)
#pragma unroll
    for (int mt = 0; mt < 4; mt++) {
        int row0 = m0 + mbase + mt * 16 + g;
        int row1 = row0 + 8;
#pragma unroll
        for (int nt = 0; nt < 4; nt++) {
            int col0 = nb + nbase + nt * 8 + 2 * tig;
            float bi0 = bias[col0], bi1 = bias[col0 + 1];
            int h0 = col0 / HDD, d0 = col0 % HDD;
            int h1 = (col0 + 1) / HDD, d1 = (col0 + 1) % HDD;
            if (row0 < NROWS) {
                int b = row0 / LL, l = row0 % LL;
                out[(((size_t)(b * NHD + h0)) * LL + l) * HDD + d0] = f2tf32(acc[mt][nt][0] + bi0);
                out[(((size_t)(b * NHD + h1)) * LL + l) * HDD + d1] = f2tf32(acc[mt][nt][1] + bi1);
            }
            if (row1 < NROWS) {
                int b = row1 / LL, l = row1 % LL;
                out[(((size_t)(b * NHD + h0)) * LL + l) * HDD + d0] = f2tf32(acc[mt][nt][2] + bi0);
                out[(((size_t)(b * NHD + h1)) * LL + l) * HDD + d1] = f2tf32(acc[mt][nt][3] + bi1);
            }
        }
    }
}

// ---- wo GEMM + per-channel stats: grid (256, 6) ----
__global__ __launch_bounds__(256, 2) void wo_gemm_kernel(const float* __restrict__ bo)
{
    GEMM_PROLOG();

    int nb = blockIdx.y * 128;
    __shared__ float scol[128];
    __shared__ float scolq[128];
    if (tid < 128) { scol[tid] = 0.f; scolq[tid] = 0.f; }

    const float* arowp[4];
    const float* wrowp[4];
#pragma unroll
    for (int u = 0; u < 4; u++) {
        int row = m0 + r0i + u * 32;
        if (row >= NROWS) row = 0;
        arowp[u] = g_ctx + (size_t)row * HH + kg * 4;
        wrowp[u] = g_wc + (size_t)3 * WELEMS + (size_t)(nb + r0i + u * 32) * HH + kg * 4;
    }

    GEMM_MAINLOOP();

#pragma unroll
    for (int nt = 0; nt < 4; nt++) {
        int nl0 = nbase + nt * 8 + 2 * tig;
        int n0 = nb + nl0;
        float bi0 = bo[n0], bi1 = bo[n0 + 1];
        float s0 = 0.f, q0 = 0.f, s1 = 0.f, q1 = 0.f;
#pragma unroll
        for (int mt = 0; mt < 4; mt++) {
            int row0 = m0 + mbase + mt * 16 + g;
            int row1 = row0 + 8;
            if (row0 < NROWS) {
                float v0 = acc[mt][nt][0] + bi0;
                float v1 = acc[mt][nt][1] + bi1;
                g_ao[(size_t)row0 * HH + n0]     = v0;
                g_ao[(size_t)row0 * HH + n0 + 1] = v1;
                s0 += v0; q0 += v0 * v0; s1 += v1; q1 += v1 * v1;
            }
            if (row1 < NROWS) {
                float v0 = acc[mt][nt][2] + bi0;
                float v1 = acc[mt][nt][3] + bi1;
                g_ao[(size_t)row1 * HH + n0]     = v0;
                g_ao[(size_t)row1 * HH + n0 + 1] = v1;
                s0 += v0; q0 += v0 * v0; s1 += v1; q1 += v1 * v1;
            }
        }
        atomicAdd(&scol[nl0], s0);      atomicAdd(&scolq[nl0], q0);
        atomicAdd(&scol[nl0 + 1], s1);  atomicAdd(&scolq[nl0 + 1], q1);
    }
    __syncthreads();
    if (tid < 128) {
        atomicAdd(&g_chsum[nb + tid], (double)scol[tid]);
        atomicAdd(&g_chsumsq[nb + tid], (double)scolq[tid]);
    }
}

// ============================================================================
// TF32 MMA flash attention; K/V/Q staged via cp.async (inputs pre-rounded).
// ============================================================================
#define KS_LD 100
#define VS_LD 104
#define PS_LD 68
#define ATTN_SMEM ((64*KS_LD + 64*VS_LD + 64*PS_LD) * 4)

__global__ __launch_bounds__(128) void attn_kernel()
{
    extern __shared__ float sm[];
    float (*Ks)[KS_LD] = (float (*)[KS_LD])sm;
    float (*Vs)[VS_LD] = (float (*)[VS_LD])(sm + 64 * KS_LD);
    float (*Ps)[PS_LD] = (float (*)[PS_LD])(sm + 64 * KS_LD + 64 * VS_LD);
    uint32_t ks_u = (uint32_t)__cvta_generic_to_shared(sm);
    uint32_t vs_u = ks_u + 64 * KS_LD * 4;

    int qt = blockIdx.x;
    int bh = blockIdx.y;
    int b = bh >> 3, h = bh & 7;
    const float* Q = g_q + (size_t)bh * LL * HDD;
    const float* K = g_k + (size_t)bh * LL * HDD;
    const float* V = g_v + (size_t)bh * LL * HDD;

    int tid  = threadIdx.x;
    int lane = tid & 31, warp = tid >> 5;
    int g = lane >> 2, tig = lane & 3;
    int mrow = warp * 16;

    // stage Q tile (64 x 96) via cp.async into Ks
    for (int idx = tid; idx < 64 * 24; idx += 128) {
        int r = idx / 24, c16 = idx % 24;
        int qg = qt * 64 + r; if (qg > LL - 1) qg = LL - 1;
        cpa16(ks_u + r * (KS_LD * 4) + c16 * 16, Q + (size_t)qg * HDD + c16 * 4);
    }
    asm volatile("cp.async.commit_group;");
    asm volatile("cp.async.wait_group 0;");
    __syncthreads();

    unsigned qa[12][4];
#pragma unroll
    for (int ks = 0; ks < 12; ks++) {
        qa[ks][0] = uldf(&Ks[mrow + g    ][ks * 8 + tig    ]);
        qa[ks][1] = uldf(&Ks[mrow + g + 8][ks * 8 + tig    ]);
        qa[ks][2] = uldf(&Ks[mrow + g    ][ks * 8 + tig + 4]);
        qa[ks][3] = uldf(&Ks[mrow + g + 8][ks * 8 + tig + 4]);
    }

    float O[12][4];
#pragma unroll
    for (int nt = 0; nt < 12; nt++)
#pragma unroll
        for (int c = 0; c < 4; c++) O[nt][c] = 0.f;
    float m0v = -1e30f, m1v = -1e30f, l0 = 0.f, l1 = 0.f;

    const float scale = 0.10206207261596575f;

    for (int kt = 0; kt < 8; kt++) {
        int ktb = kt * 64;
        __syncthreads();
        for (int idx = tid; idx < 64 * 24; idx += 128) {
            int r = idx / 24, c16 = idx % 24;
            int kg2 = ktb + r;
            int sz = (kg2 < LL) ? 16 : 0;
            int kc = (kg2 < LL) ? kg2 : (LL - 1);
            cpa16z(ks_u + r * (KS_LD * 4) + c16 * 16, K + (size_t)kc * HDD + c16 * 4, sz);
            cpa16z(vs_u + r * (VS_LD * 4) + c16 * 16, V + (size_t)kc * HDD + c16 * 4, sz);
        }
        asm volatile("cp.async.commit_group;");
        asm volatile("cp.async.wait_group 0;");
        __syncthreads();

        float s[8][4];
#pragma unroll
        for (int nt = 0; nt < 8; nt++)
#pragma unroll
            for (int c = 0; c < 4; c++) s[nt][c] = 0.f;

#pragma unroll
        for (int ks = 0; ks < 12; ks++) {
#pragma unroll
            for (int nt = 0; nt < 8; nt++) {
                unsigned b0 = uldf(&Ks[nt * 8 + g][ks * 8 + tig    ]);
                unsigned b1 = uldf(&Ks[nt * 8 + g][ks * 8 + tig + 4]);
                mma_tf32(s[nt], qa[ks][0], qa[ks][1], qa[ks][2], qa[ks][3], b0, b1);
            }
        }

#pragma unroll
        for (int nt = 0; nt < 8; nt++) {
            int col = ktb + nt * 8 + 2 * tig;
            s[nt][0] = (col     < LL) ? s[nt][0] * scale : -1e30f;
            s[nt][1] = (col + 1 < LL) ? s[nt][1] * scale : -1e30f;
            s[nt][2] = (col     < LL) ? s[nt][2] * scale : -1e30f;
            s[nt][3] = (col + 1 < LL) ? s[nt][3] * scale : -1e30f;
        }

        float mt0 = -1e30f, mt1 = -1e30f;
#pragma unroll
        for (int nt = 0; nt < 8; nt++) {
            mt0 = fmaxf(mt0, fmaxf(s[nt][0], s[nt][1]));
            mt1 = fmaxf(mt1, fmaxf(s[nt][2], s[nt][3]));
        }
        mt0 = fmaxf(mt0, __shfl_xor_sync(0xffffffffu, mt0, 1));
        mt0 = fmaxf(mt0, __shfl_xor_sync(0xffffffffu, mt0, 2));
        mt1 = fmaxf(mt1, __shfl_xor_sync(0xffffffffu, mt1, 1));
        mt1 = fmaxf(mt1, __shfl_xor_sync(0xffffffffu, mt1, 2));

        float mn0 = fmaxf(m0v, mt0), mn1 = fmaxf(m1v, mt1);
        float al0 = expf(m0v - mn0), al1 = expf(m1v - mn1);
        m0v = mn0; m1v = mn1;

        float rs0 = 0.f, rs1 = 0.f;
#pragma unroll
        for (int nt = 0; nt < 8; nt++) {
            float p0 = expf(s[nt][0] - mn0);
            float p1 = expf(s[nt][1] - mn0);
            float p2 = expf(s[nt][2] - mn1);
            float p3 = expf(s[nt][3] - mn1);
            rs0 += p0 + p1; rs1 += p2 + p3;
            int col = nt * 8 + 2 * tig;
            Ps[mrow + g    ][col] = f2tf32(p0); Ps[mrow + g    ][col + 1] = f2tf32(p1);
            Ps[mrow + g + 8][col] = f2tf32(p2); Ps[mrow + g + 8][col + 1] = f2tf32(p3);
        }
        rs0 += __shfl_xor_sync(0xffffffffu, rs0, 1);
        rs0 += __shfl_xor_sync(0xffffffffu, rs0, 2);
        rs1 += __shfl_xor_sync(0xffffffffu, rs1, 1);
        rs1 += __shfl_xor_sync(0xffffffffu, rs1, 2);
        l0 = l0 * al0 + rs0;
        l1 = l1 * al1 + rs1;

#pragma unroll
        for (int nt = 0; nt < 12; nt++) {
            O[nt][0] *= al0; O[nt][1] *= al0;
            O[nt][2] *= al1; O[nt][3] *= al1;
        }
        __syncwarp();

#pragma unroll
        for (int ks = 0; ks < 8; ks++) {
            unsigned pa0 = uldf(&Ps[mrow + g    ][ks * 8 + tig    ]);
            unsigned pa1 = uldf(&Ps[mrow + g + 8][ks * 8 + tig    ]);
            unsigned pa2 = uldf(&Ps[mrow + g    ][ks * 8 + tig + 4]);
            unsigned pa3 = uldf(&Ps[mrow + g + 8][ks * 8 + tig + 4]);
#pragma unroll
            for (int nt = 0; nt < 12; nt++) {
                unsigned b0 = uldf(&Vs[ks * 8 + tig    ][nt * 8 + g]);
                unsigned b1 = uldf(&Vs[ks * 8 + tig + 4][nt * 8 + g]);
                mma_tf32(O[nt], pa0, pa1, pa2, pa3, b0, b1);
            }
        }
    }

    // write tf32-rounded ctx (consumed by wo GEMM)
    float inv0 = 1.0f / l0, inv1 = 1.0f / l1;
    int qg0 = qt * 64 + mrow + g;
    int qg1 = qg0 + 8;
    size_t base0 = ((size_t)(b * LL + qg0)) * HH + h * HDD;
    size_t base1 = ((size_t)(b * LL + qg1)) * HH + h * HDD;
#pragma unroll
    for (int nt = 0; nt < 12; nt++) {
        int d0 = nt * 8 + 2 * tig;
        if (qg0 < LL) {
            g_ctx[base0 + d0]     = f2tf32(O[nt][0] * inv0);
            g_ctx[base0 + d0 + 1] = f2tf32(O[nt][1] * inv0);
        }
        if (qg1 < LL) {
            g_ctx[base1 + d0]     = f2tf32(O[nt][2] * inv1);
            g_ctx[base1 + d0 + 1] = f2tf32(O[nt][3] * inv1);
        }
    }
}

// ---------------- finalize: mu/var -> g, C0 --------------------------------
__global__ void finalize_kernel(const float* __restrict__ gamma,
                                const float* __restrict__ beta,
                                const float* __restrict__ w_out,
                                const float* __restrict__ b_out)
{
    __shared__ float red[HH];
    int h = threadIdx.x;
    const double N = (double)NROWS;
    double mu  = g_chsum[h] / N;
    double var = g_chsumsq[h] / N - mu * mu;
    double inv = 1.0 / sqrt(var + 1e-5);
    float g = w_out[h] * gamma[h] * (float)inv;
    g_g[h] = g;
    red[h] = w_out[h] * beta[h] - g * (float)mu;
    __syncthreads();
    if (h < 256) red[h] += red[h + 512];
    __syncthreads();
    for (int s = 256; s > 0; s >>= 1) {
        if (h < s) red[h] += red[h + s];
        __syncthreads();
    }
    if (h == 0) g_c0 = red[0] + b_out[0];
}

// ---------------- fv = c . w_out + attn_out . g + C0 -----------------------
__global__ __launch_bounds__(256) void fv_kernel(const float* __restrict__ cols,
                                                 const float* __restrict__ w_out)
{
    int warp = (blockIdx.x * 256 + threadIdx.x) >> 5;
    int lane = threadIdx.x & 31;
    if (warp >= NROWS) return;
    int b = warp / LL, l = warp % LL;
    const float* crow = cols + ((size_t)(b * SS) + l + 1) * HH;
    const float* arow = g_ao + (size_t)warp * HH;
    float s = 0.f;
    for (int k = lane; k < HH; k += 32)
        s += crow[k] * w_out[k] + arow[k] * g_g[k];
#pragma unroll
    for (int o = 16; o > 0; o >>= 1) s += __shfl_xor_sync(0xffffffffu, s, o);
    if (lane == 0) g_fv[warp] = s + g_c0;
}

// ---------------- segment pooling -------------------------------------------
__global__ void segpool_kernel(const int* __restrict__ ids, float* __restrict__ out, int nseg)
{
    int b = blockIdx.x;
    __shared__ int sc[512];
    __shared__ float ssum[32];
    __shared__ float scnt[32];
    int l = threadIdx.x;
    int ic = 0;
    if (l < LL) ic = (ids[b * SS + l] == COMMA_ID) ? 1 : 0;
    sc[l] = ic;
    __syncthreads();
    for (int off = 1; off < 512; off <<= 1) {
        int v = (l >= off) ? sc[l - off] : 0;
        __syncthreads();
        sc[l] += v;
        __syncthreads();
    }
    int seg = sc[l] - ic;
    if (l < 32) { ssum[l] = 0.f; scnt[l] = 0.f; }
    __syncthreads();
    if (l >= 1 && l < LL && !ic && seg < nseg) {
        atomicAdd(&ssum[seg], g_fv[(size_t)b * LL + l]);
        atomicAdd(&scnt[seg], 1.0f);
    }
    __syncthreads();
    if (l < nseg) out[b * nseg + l] = ssum[l] / fmaxf(scnt[l], 1.0f);
}

// ---------------- launch -----------------------------------------------------
extern "C" void kernel_launch(void* const* d_in, const int* in_sizes, int n_in,
                              void* d_out, int out_size)
{
    const float* text   = (const float*)d_in[0];
    const float* cols   = (const float*)d_in[1];
    const float* wq     = (const float*)d_in[2];
    const float* wk     = (const float*)d_in[3];
    const float* wv     = (const float*)d_in[4];
    const float* bq     = (const float*)d_in[5];
    const float* bk     = (const float*)d_in[6];
    const float* bv     = (const float*)d_in[7];
    const float* wo     = (const float*)d_in[8];
    const float* bo     = (const float*)d_in[9];
    const float* gamma  = (const float*)d_in[10];
    const float* beta   = (const float*)d_in[11];
    const float* w_out  = (const float*)d_in[12];
    const float* b_out  = (const float*)d_in[13];
    const int*   ids    = (const int*)d_in[14];
    float* out = (float*)d_out;
    int nseg = out_size / BB;   // 17

    static int attrs_set = 0;
    if (!attrs_set) {
        cudaFuncSetAttribute(attn_kernel,
            cudaFuncAttributeMaxDynamicSharedMemorySize, ATTN_SMEM);
        cudaFuncSetAttribute(qkv_gemm_kernel,
            cudaFuncAttributeMaxDynamicSharedMemorySize, GEMM_SMEM);
        cudaFuncSetAttribute(wo_gemm_kernel,
            cudaFuncAttributeMaxDynamicSharedMemorySize, GEMM_SMEM);
        attrs_set = 1;
    }

    zero_stats_kernel<<<1, HH>>>();
    convert_acts_kernel<<<dim3((NROWS * 192 + 255) / 256, 2), 256>>>(text, cols);
    convert_w_kernel<<<dim3((WELEMS / 4 + 255) / 256, 4), 256>>>(wq, wk, wv, wo);
    qkv_gemm_kernel<<<dim3(256, 18), 256, GEMM_SMEM>>>(bq, bk, bv);
    attn_kernel<<<dim3(8, 512), 128, ATTN_SMEM>>>();
    wo_gemm_kernel<<<dim3(256, 6), 256, GEMM_SMEM>>>(bo);
    finalize_kernel<<<1, HH>>>(gamma, beta, w_out, b_out);
    fv_kernel<<<(NROWS + 7) / 8, 256>>>(cols, w_out);
    segpool_kernel<<<BB, 512>>>(ids, out, nseg);
}